// round 2
// baseline (speedup 1.0000x reference)
#include <cuda_runtime.h>

#define BB 8
#define SS 2048
#define DD 1024
#define MS (BB * SS)   // 16384

// Scratch: device globals (no cudaMalloc allowed)
__device__ float g_q[(size_t)MS * DD];          // 64 MB
__device__ float g_k[(size_t)MS * DD];          // 64 MB
__device__ float g_v[(size_t)MS * DD];          // 64 MB
__device__ float g_s[(size_t)BB * SS * SS];     // 128 MB (scores -> weights in place)

// ---------------------------------------------------------------------------
// Pass 1: Q/K/V projection. NN GEMM, M=16384, N=1024, K=1024.
// blockIdx.z selects which weight matrix / output.
// Tile 128x128x8, 256 threads, 8x8 per thread.
// ---------------------------------------------------------------------------
__global__ __launch_bounds__(256) void qkv_kernel(
    const float* __restrict__ x,
    const float* __restrict__ Wq,
    const float* __restrict__ Wk,
    const float* __restrict__ Wv)
{
    const float* W = (blockIdx.z == 0) ? Wq : (blockIdx.z == 1) ? Wk : Wv;
    float* O       = (blockIdx.z == 0) ? g_q : (blockIdx.z == 1) ? g_k : g_v;

    __shared__ float As[8][128];
    __shared__ float Bs[8][128];

    const int tid = threadIdx.x;
    const int tx = tid & 15;
    const int ty = tid >> 4;
    const int m0 = blockIdx.y * 128;
    const int n0 = blockIdx.x * 128;

    const int arow = tid >> 1;          // 0..127
    const int acol = (tid & 1) * 4;     // 0 or 4
    const int brow = tid >> 5;          // 0..7
    const int bcol = (tid & 31) * 4;    // 0..124

    float acc[8][8] = {};

    for (int k0 = 0; k0 < DD; k0 += 8) {
        float4 av = *(const float4*)(x + (size_t)(m0 + arow) * DD + k0 + acol);
        As[acol + 0][arow] = av.x;
        As[acol + 1][arow] = av.y;
        As[acol + 2][arow] = av.z;
        As[acol + 3][arow] = av.w;
        *(float4*)&Bs[brow][bcol] =
            *(const float4*)(W + (size_t)(k0 + brow) * DD + n0 + bcol);
        __syncthreads();
#pragma unroll
        for (int kk = 0; kk < 8; kk++) {
            float a[8], b[8];
            *(float4*)(a)     = *(const float4*)&As[kk][ty * 8];
            *(float4*)(a + 4) = *(const float4*)&As[kk][ty * 8 + 4];
            *(float4*)(b)     = *(const float4*)&Bs[kk][tx * 8];
            *(float4*)(b + 4) = *(const float4*)&Bs[kk][tx * 8 + 4];
#pragma unroll
            for (int i = 0; i < 8; i++)
#pragma unroll
                for (int j = 0; j < 8; j++)
                    acc[i][j] = fmaf(a[i], b[j], acc[i][j]);
        }
        __syncthreads();
    }
#pragma unroll
    for (int i = 0; i < 8; i++) {
        int m = m0 + ty * 8 + i;
        float* cp = O + (size_t)m * DD + n0 + tx * 8;
        *(float4*)cp       = make_float4(acc[i][0], acc[i][1], acc[i][2], acc[i][3]);
        *(float4*)(cp + 4) = make_float4(acc[i][4], acc[i][5], acc[i][6], acc[i][7]);
    }
}

// ---------------------------------------------------------------------------
// Pass 2: scores[b,i,j] = (q[b,i,:] . k[b,j,:]) / 32  (NT GEMM, per batch).
// Only lower-triangle 128x128 block tiles (bj <= bi) are computed.
// Upper-triangle region of g_s is never written and never read.
// ---------------------------------------------------------------------------
__global__ __launch_bounds__(256) void scores_kernel()
{
    const int bi = blockIdx.y;
    const int bj = blockIdx.x;
    if (bj > bi) return;
    const int b = blockIdx.z;

    const float* qb = g_q + (size_t)b * SS * DD;
    const float* kb = g_k + (size_t)b * SS * DD;
    float*       sb = g_s + (size_t)b * SS * SS;

    __shared__ float As[8][128];
    __shared__ float Bs[8][128];

    const int tid = threadIdx.x;
    const int tx = tid & 15;
    const int ty = tid >> 4;
    const int i0 = bi * 128;
    const int j0 = bj * 128;

    const int arow = tid >> 1;
    const int acol = (tid & 1) * 4;

    float acc[8][8] = {};

    for (int k0 = 0; k0 < DD; k0 += 8) {
        float4 av = *(const float4*)(qb + (size_t)(i0 + arow) * DD + k0 + acol);
        As[acol + 0][arow] = av.x;
        As[acol + 1][arow] = av.y;
        As[acol + 2][arow] = av.z;
        As[acol + 3][arow] = av.w;
        float4 bv = *(const float4*)(kb + (size_t)(j0 + arow) * DD + k0 + acol);
        Bs[acol + 0][arow] = bv.x;
        Bs[acol + 1][arow] = bv.y;
        Bs[acol + 2][arow] = bv.z;
        Bs[acol + 3][arow] = bv.w;
        __syncthreads();
#pragma unroll
        for (int kk = 0; kk < 8; kk++) {
            float a[8], b2[8];
            *(float4*)(a)      = *(const float4*)&As[kk][ty * 8];
            *(float4*)(a + 4)  = *(const float4*)&As[kk][ty * 8 + 4];
            *(float4*)(b2)     = *(const float4*)&Bs[kk][tx * 8];
            *(float4*)(b2 + 4) = *(const float4*)&Bs[kk][tx * 8 + 4];
#pragma unroll
            for (int i = 0; i < 8; i++)
#pragma unroll
                for (int j = 0; j < 8; j++)
                    acc[i][j] = fmaf(a[i], b2[j], acc[i][j]);
        }
        __syncthreads();
    }
    const float scale = 0.03125f;   // 1/sqrt(1024)
#pragma unroll
    for (int i = 0; i < 8; i++) {
        int irow = i0 + ty * 8 + i;
        float* cp = sb + (size_t)irow * SS + j0 + tx * 8;
        *(float4*)cp       = make_float4(acc[i][0] * scale, acc[i][1] * scale,
                                         acc[i][2] * scale, acc[i][3] * scale);
        *(float4*)(cp + 4) = make_float4(acc[i][4] * scale, acc[i][5] * scale,
                                         acc[i][6] * scale, acc[i][7] * scale);
    }
}

// ---------------------------------------------------------------------------
// Pass 3: softmax over axis=1 (query axis) -> column-wise softmax.
// Column j normalizes over rows i in [j, S). Block = 32 columns x 8 row-lanes.
// Row-major loads across 32 adjacent columns => coalesced.
// In-place: g_s becomes the weight matrix (lower triangle only).
// ---------------------------------------------------------------------------
__global__ void softmax_kernel()
{
    const int b = blockIdx.y;
    float* sb = g_s + (size_t)b * SS * SS;
    const int tx = threadIdx.x;            // 0..31 (column within tile)
    const int ty = threadIdx.y;            // 0..7  (row lane)
    const int j0 = blockIdx.x * 32;
    const int j = j0 + tx;

    __shared__ float red[8][32];

    // pass 1: max over valid rows i >= j
    float mx = -INFINITY;
    for (int i = j0 + ty; i < SS; i += 8) {
        float v = sb[(size_t)i * SS + j];
        if (i >= j) mx = fmaxf(mx, v);
    }
    red[ty][tx] = mx;
    __syncthreads();
    if (ty == 0) {
        float m = red[0][tx];
#pragma unroll
        for (int r = 1; r < 8; r++) m = fmaxf(m, red[r][tx]);
        red[0][tx] = m;
    }
    __syncthreads();
    mx = red[0][tx];
    __syncthreads();

    // pass 2: sum of exp
    float sum = 0.f;
    for (int i = j0 + ty; i < SS; i += 8) {
        float v = sb[(size_t)i * SS + j];
        if (i >= j) sum += __expf(v - mx);
    }
    red[ty][tx] = sum;
    __syncthreads();
    if (ty == 0) {
        float s = 0.f;
#pragma unroll
        for (int r = 0; r < 8; r++) s += red[r][tx];
        red[0][tx] = 1.0f / s;
    }
    __syncthreads();
    float inv = red[0][tx];

    // pass 3: normalize in place (only valid rows)
    for (int i = j0 + ty; i < SS; i += 8) {
        if (i >= j) {
            float v = sb[(size_t)i * SS + j];
            sb[(size_t)i * SS + j] = __expf(v - mx) * inv;
        }
    }
}

// ---------------------------------------------------------------------------
// Pass 4: out[b,i,e] = sum_{j<=i} w[b,i,j] * v[b,j,e]  (NN GEMM, per batch).
// k-loop truncated at j < m0+128; per-element predicate (j<=i) on the
// diagonal block zeroes the un-normalized upper entries.
// ---------------------------------------------------------------------------
__global__ __launch_bounds__(256) void out_kernel(float* __restrict__ out)
{
    const int b = blockIdx.z;
    const float* wb = g_s + (size_t)b * SS * SS;
    const float* vb = g_v + (size_t)b * SS * DD;
    float*       ob = out + (size_t)b * SS * DD;

    __shared__ float As[8][128];
    __shared__ float Bs[8][128];

    const int tid = threadIdx.x;
    const int tx = tid & 15;
    const int ty = tid >> 4;
    const int m0 = blockIdx.y * 128;
    const int n0 = blockIdx.x * 128;

    const int arow = tid >> 1;
    const int acol = (tid & 1) * 4;
    const int brow = tid >> 5;
    const int bcol = (tid & 31) * 4;

    float acc[8][8] = {};
    const int kmax = m0 + 128;   // causal: j <= max row in this tile

    for (int k0 = 0; k0 < kmax; k0 += 8) {
        const int irow = m0 + arow;
        const int jc = k0 + acol;
        float4 av = *(const float4*)(wb + (size_t)irow * SS + jc);
        As[acol + 0][arow] = (jc + 0 <= irow) ? av.x : 0.f;
        As[acol + 1][arow] = (jc + 1 <= irow) ? av.y : 0.f;
        As[acol + 2][arow] = (jc + 2 <= irow) ? av.z : 0.f;
        As[acol + 3][arow] = (jc + 3 <= irow) ? av.w : 0.f;
        *(float4*)&Bs[brow][bcol] =
            *(const float4*)(vb + (size_t)(k0 + brow) * DD + n0 + bcol);
        __syncthreads();
#pragma unroll
        for (int kk = 0; kk < 8; kk++) {
            float a[8], b2[8];
            *(float4*)(a)      = *(const float4*)&As[kk][ty * 8];
            *(float4*)(a + 4)  = *(const float4*)&As[kk][ty * 8 + 4];
            *(float4*)(b2)     = *(const float4*)&Bs[kk][tx * 8];
            *(float4*)(b2 + 4) = *(const float4*)&Bs[kk][tx * 8 + 4];
#pragma unroll
            for (int i = 0; i < 8; i++)
#pragma unroll
                for (int j = 0; j < 8; j++)
                    acc[i][j] = fmaf(a[i], b2[j], acc[i][j]);
        }
        __syncthreads();
    }
#pragma unroll
    for (int i = 0; i < 8; i++) {
        int m = m0 + ty * 8 + i;
        float* cp = ob + (size_t)m * DD + n0 + tx * 8;
        *(float4*)cp       = make_float4(acc[i][0], acc[i][1], acc[i][2], acc[i][3]);
        *(float4*)(cp + 4) = make_float4(acc[i][4], acc[i][5], acc[i][6], acc[i][7]);
    }
}

// ---------------------------------------------------------------------------
extern "C" void kernel_launch(void* const* d_in, const int* in_sizes, int n_in,
                              void* d_out, int out_size)
{
    const float* x  = (const float*)d_in[0];
    const float* Wq = (const float*)d_in[1];
    const float* Wk = (const float*)d_in[2];
    const float* Wv = (const float*)d_in[3];
    float* out = (float*)d_out;

    // Pass 1: Q, K, V projections
    qkv_kernel<<<dim3(DD / 128, MS / 128, 3), 256>>>(x, Wq, Wk, Wv);

    // Pass 2: causal scores (lower-triangle block tiles only)
    scores_kernel<<<dim3(SS / 128, SS / 128, BB), 256>>>();

    // Pass 3: column-wise (axis=1) softmax, in place
    softmax_kernel<<<dim3(SS / 32, BB), dim3(32, 8)>>>();

    // Pass 4: weights @ V with causal truncation
    out_kernel<<<dim3(DD / 128, SS / 128, BB), 256>>>(out);
}

// round 4
// speedup vs baseline: 2.8050x; 2.8050x over previous
#include <cuda_runtime.h>
#include <cuda_bf16.h>
#include <cstdint>
#include <cstring>

#define BB 8
#define SS 2048
#define DD 1024
#define MS (BB * SS)   // 16384

// ---------------- scratch (device globals; no cudaMalloc allowed) ----------
__device__ float g_q [(size_t)MS * DD];         // 64 MB
__device__ float g_k [(size_t)MS * DD];         // 64 MB
__device__ float g_v [(size_t)MS * DD];         // 64 MB
__device__ float g_vt[(size_t)BB * DD * SS];    // 64 MB  v transposed per batch
__device__ float g_wt[(size_t)3 * DD * DD];     // 12 MB  Wq/Wk/Wv transposed
__device__ float g_s [(size_t)BB * SS * SS];    // 128 MB scores -> weights

// ---------------- smem geometry --------------------------------------------
// bf16 tile 128 rows x 32 k, row stride 80B (5*16B; 5 coprime 8 => ldmatrix
// conflict-free). 4 tiles per stage: A_hi, A_lo, B_hi, B_lo. 2 stages.
#define ROWB    80
#define TILE_B  (128 * ROWB)        // 10240
#define STAGE_B (4 * TILE_B)        // 40960
#define SMEM_BYTES (2 * STAGE_B)    // 81920

// ---------------- PTX helpers ----------------------------------------------
__device__ __forceinline__ uint32_t smem_u32(const void* p) {
    uint32_t a;
    asm("{ .reg .u64 t; cvta.to.shared.u64 t, %1; cvt.u32.u64 %0, t; }"
        : "=r"(a) : "l"(p));
    return a;
}
__device__ __forceinline__ void ldsm_x4(uint32_t* r, uint32_t addr) {
    asm volatile("ldmatrix.sync.aligned.m8n8.x4.shared.b16 {%0,%1,%2,%3}, [%4];"
        : "=r"(r[0]), "=r"(r[1]), "=r"(r[2]), "=r"(r[3]) : "r"(addr));
}
__device__ __forceinline__ void mma16816(float* c, const uint32_t* a,
                                         const uint32_t* b) {
    asm volatile(
        "mma.sync.aligned.m16n8k16.row.col.f32.bf16.bf16.f32 "
        "{%0,%1,%2,%3}, {%4,%5,%6,%7}, {%8,%9}, {%0,%1,%2,%3};"
        : "+f"(c[0]), "+f"(c[1]), "+f"(c[2]), "+f"(c[3])
        : "r"(a[0]), "r"(a[1]), "r"(a[2]), "r"(a[3]), "r"(b[0]), "r"(b[1]));
}

// fp32 -> (hi, lo) bf16 split; hi 8B at p+off, lo 8B at p+TILE_B+off
__device__ __forceinline__ void cvt_store(char* p, uint32_t off, float4 v) {
    __nv_bfloat162 h01 = __floats2bfloat162_rn(v.x, v.y);
    __nv_bfloat162 h23 = __floats2bfloat162_rn(v.z, v.w);
    float2 f01 = __bfloat1622float2(h01);
    float2 f23 = __bfloat1622float2(h23);
    __nv_bfloat162 l01 = __floats2bfloat162_rn(v.x - f01.x, v.y - f01.y);
    __nv_bfloat162 l23 = __floats2bfloat162_rn(v.z - f23.x, v.w - f23.y);
    uint32_t uh0, uh1, ul0, ul1;
    memcpy(&uh0, &h01, 4); memcpy(&uh1, &h23, 4);
    memcpy(&ul0, &l01, 4); memcpy(&ul1, &l23, 4);
    *(uint2*)(p + off)          = make_uint2(uh0, uh1);
    *(uint2*)(p + TILE_B + off) = make_uint2(ul0, ul1);
}

// ---------------------------------------------------------------------------
// 128x128 tile GEMM:  C[m][n] = scale * sum_k A[m][k] * B[n][k]
// A,B fp32 K-major; split-bf16 mma.sync; kelems multiple of 32.
// ---------------------------------------------------------------------------
__device__ __forceinline__ void gemm_core(
    const float* __restrict__ A, int lda,
    const float* __restrict__ B, int ldb,
    float* __restrict__ C, int ldc,
    int kelems, float scale)
{
    extern __shared__ char sm[];
    const uint32_t sbase = smem_u32(sm);

    const int tid  = threadIdx.x;
    const int lane = tid & 31;
    const int wid  = tid >> 5;
    const int wm   = (wid & 1) * 64;    // warp m base (2 warps over m)
    const int wn   = (wid >> 1) * 32;   // warp n base (4 warps over n)

    // fill indices: idx = tid + i*256 -> row = r0 + 32*i, q = float4 slot
    const int r0 = tid >> 3;
    const int q  = tid & 7;

    // ldmatrix base offsets
    const uint32_t a_off = (uint32_t)(wm + (lane & 15)) * ROWB + (lane >> 4) * 16;
    const uint32_t b_off = (uint32_t)(wn + (lane & 7) + ((lane >> 4) & 1) * 8) * ROWB
                         + ((lane >> 3) & 1) * 16;

    float acc[4][4][4] = {};

    const int nc = kelems >> 5;

    // prologue: chunk 0 -> stage 0
    {
        char* st = sm;
#pragma unroll
        for (int i = 0; i < 4; i++) {
            const int row = r0 + 32 * i;
            const uint32_t off = (uint32_t)row * ROWB + q * 8;
            float4 va = *(const float4*)(A + (size_t)row * lda + q * 4);
            cvt_store(st, off, va);
            float4 vb = *(const float4*)(B + (size_t)row * ldb + q * 4);
            cvt_store(st + 2 * TILE_B, off, vb);
        }
    }
    __syncthreads();

    for (int c = 0; c < nc; c++) {
        const int s = c & 1;
        const bool more = (c + 1 < nc);

        // prefetch next chunk into registers
        float4 va[4], vb[4];
        if (more) {
            const int k0 = (c + 1) << 5;
#pragma unroll
            for (int i = 0; i < 4; i++) {
                const int row = r0 + 32 * i;
                va[i] = *(const float4*)(A + (size_t)row * lda + k0 + q * 4);
                vb[i] = *(const float4*)(B + (size_t)row * ldb + k0 + q * 4);
            }
        }

        // MMA on stage s (two k16 steps)
        const uint32_t sA  = sbase + s * STAGE_B;
        const uint32_t sAl = sA + TILE_B;
        const uint32_t sB  = sA + 2 * TILE_B;
        const uint32_t sBl = sA + 3 * TILE_B;
#pragma unroll
        for (int kk = 0; kk < 2; kk++) {
            const uint32_t ka = a_off + kk * 32;
            const uint32_t kb = b_off + kk * 32;
            uint32_t ah[4][4], al[4][4], bh[2][4], bl[2][4];
#pragma unroll
            for (int mt = 0; mt < 4; mt++) {
                ldsm_x4(ah[mt], sA  + ka + mt * 16 * ROWB);
                ldsm_x4(al[mt], sAl + ka + mt * 16 * ROWB);
            }
#pragma unroll
            for (int np = 0; np < 2; np++) {
                ldsm_x4(bh[np], sB  + kb + np * 16 * ROWB);
                ldsm_x4(bl[np], sBl + kb + np * 16 * ROWB);
            }
#pragma unroll
            for (int mt = 0; mt < 4; mt++)
#pragma unroll
                for (int nt = 0; nt < 4; nt++) {
                    const uint32_t* bph = &bh[nt >> 1][(nt & 1) * 2];
                    const uint32_t* bpl = &bl[nt >> 1][(nt & 1) * 2];
                    mma16816(acc[mt][nt], ah[mt], bph);
                    mma16816(acc[mt][nt], ah[mt], bpl);
                    mma16816(acc[mt][nt], al[mt], bph);
                }
        }

        // store prefetched chunk into the other stage
        if (more) {
            char* st = sm + (s ^ 1) * STAGE_B;
#pragma unroll
            for (int i = 0; i < 4; i++) {
                const int row = r0 + 32 * i;
                const uint32_t off = (uint32_t)row * ROWB + q * 8;
                cvt_store(st, off, va[i]);
                cvt_store(st + 2 * TILE_B, off, vb[i]);
            }
            __syncthreads();
        }
    }

    // epilogue: c frag layout m16n8 -> row lane>>2 (+8), col (lane&3)*2 (+1)
    const int er = lane >> 2;
    const int ec = (lane & 3) * 2;
#pragma unroll
    for (int mt = 0; mt < 4; mt++)
#pragma unroll
        for (int nt = 0; nt < 4; nt++) {
            const int r = wm + mt * 16 + er;
            const int cn = wn + nt * 8 + ec;
            float* p0 = C + (size_t)r * ldc + cn;
            float* p1 = C + (size_t)(r + 8) * ldc + cn;
            *(float2*)p0 = make_float2(acc[mt][nt][0] * scale,
                                       acc[mt][nt][1] * scale);
            *(float2*)p1 = make_float2(acc[mt][nt][2] * scale,
                                       acc[mt][nt][3] * scale);
        }
}

// ---------------------------------------------------------------------------
// Pass kernels
// ---------------------------------------------------------------------------
__global__ __launch_bounds__(256, 1) void k_qkv(const float* __restrict__ x)
{
    const int z = blockIdx.z;
    const float* Bt = g_wt + (size_t)z * DD * DD;
    float* O = (z == 0) ? g_q : (z == 1) ? g_k : g_v;
    gemm_core(x + (size_t)blockIdx.y * 128 * DD, DD,
              Bt + (size_t)blockIdx.x * 128 * DD, DD,
              O + (size_t)blockIdx.y * 128 * DD + blockIdx.x * 128, DD,
              DD, 1.0f);
}

__global__ __launch_bounds__(256, 1) void k_scores()
{
    if (blockIdx.x > blockIdx.y) return;     // causal: lower-triangle tiles
    const int b = blockIdx.z;
    gemm_core(g_q + (size_t)b * SS * DD + (size_t)blockIdx.y * 128 * DD, DD,
              g_k + (size_t)b * SS * DD + (size_t)blockIdx.x * 128 * DD, DD,
              g_s + (size_t)b * SS * SS + (size_t)blockIdx.y * 128 * SS
                  + blockIdx.x * 128, SS,
              DD, 0.03125f);                 // 1/sqrt(1024)
}

__global__ __launch_bounds__(256, 1) void k_out(float* __restrict__ out)
{
    const int b = blockIdx.z;
    const int m0 = blockIdx.y * 128;
    gemm_core(g_s + (size_t)b * SS * SS + (size_t)m0 * SS, SS,
              g_vt + (size_t)b * DD * SS + (size_t)blockIdx.x * 128 * SS, SS,
              out + (size_t)b * SS * DD + (size_t)m0 * DD + blockIdx.x * 128, DD,
              m0 + 128, 1.0f);               // causal K truncation
}

// ---------------------------------------------------------------------------
// Transpose: out[cols x rows] = in[rows x cols]^T, 32x32 smem tiles
// ---------------------------------------------------------------------------
__global__ void k_transpose(const float* __restrict__ in, float* __restrict__ out,
                            int rows, int cols, size_t in_bs, size_t out_bs)
{
    __shared__ float t[32][33];
    const float* ib = in + blockIdx.z * in_bs;
    float* ob = out + blockIdx.z * out_bs;
    const int x0 = blockIdx.x * 32, y0 = blockIdx.y * 32;
    const int tx = threadIdx.x, ty = threadIdx.y;   // 32 x 8
#pragma unroll
    for (int i = 0; i < 32; i += 8)
        t[ty + i][tx] = ib[(size_t)(y0 + ty + i) * cols + x0 + tx];
    __syncthreads();
#pragma unroll
    for (int i = 0; i < 32; i += 8)
        ob[(size_t)(x0 + ty + i) * rows + y0 + tx] = t[tx][ty + i];
}

// ---------------------------------------------------------------------------
// Column softmax over query axis (axis=1). Column j normalizes over rows
// i in [j, S). Zeroes upper-triangle entries down to the 128-aligned tile
// base so the out-pass GEMM needs no predicate.
// ---------------------------------------------------------------------------
__global__ void k_softmax()
{
    const int b = blockIdx.y;
    float* sb = g_s + (size_t)b * SS * SS;
    const int tx = threadIdx.x;                 // column within 32-tile
    const int ty = threadIdx.y;                 // row lane (8)
    const int j0 = blockIdx.x * 32;
    const int j = j0 + tx;
    const int ibase = (j0 & ~127);              // 128-aligned tile base

    __shared__ float red[8][32];

    float mx = -INFINITY;
    for (int i = ibase + ty; i < SS; i += 8) {
        float v = sb[(size_t)i * SS + j];
        if (i >= j) mx = fmaxf(mx, v);
    }
    red[ty][tx] = mx;
    __syncthreads();
    if (ty == 0) {
        float m = red[0][tx];
#pragma unroll
        for (int r = 1; r < 8; r++) m = fmaxf(m, red[r][tx]);
        red[0][tx] = m;
    }
    __syncthreads();
    mx = red[0][tx];
    __syncthreads();

    float sum = 0.f;
    for (int i = ibase + ty; i < SS; i += 8) {
        float v = sb[(size_t)i * SS + j];
        if (i >= j) sum += __expf(v - mx);
    }
    red[ty][tx] = sum;
    __syncthreads();
    if (ty == 0) {
        float s = 0.f;
#pragma unroll
        for (int r = 0; r < 8; r++) s += red[r][tx];
        red[0][tx] = 1.0f / s;
    }
    __syncthreads();
    const float inv = red[0][tx];

    for (int i = ibase + ty; i < SS; i += 8) {
        float v = sb[(size_t)i * SS + j];
        sb[(size_t)i * SS + j] = (i >= j) ? __expf(v - mx) * inv : 0.0f;
    }
}

// ---------------------------------------------------------------------------
extern "C" void kernel_launch(void* const* d_in, const int* in_sizes, int n_in,
                              void* d_out, int out_size)
{
    const float* x  = (const float*)d_in[0];
    const float* Wq = (const float*)d_in[1];
    const float* Wk = (const float*)d_in[2];
    const float* Wv = (const float*)d_in[3];
    float* out = (float*)d_out;

    cudaFuncSetAttribute(k_qkv,    cudaFuncAttributeMaxDynamicSharedMemorySize, SMEM_BYTES);
    cudaFuncSetAttribute(k_scores, cudaFuncAttributeMaxDynamicSharedMemorySize, SMEM_BYTES);
    cudaFuncSetAttribute(k_out,    cudaFuncAttributeMaxDynamicSharedMemorySize, SMEM_BYTES);

    float* wt;   cudaGetSymbolAddress((void**)&wt, g_wt);
    float* vsrc; cudaGetSymbolAddress((void**)&vsrc, g_v);
    float* vt;   cudaGetSymbolAddress((void**)&vt, g_vt);

    dim3 tb(32, 8);

    // W transposes: wt[n][k] = W[k][n]
    k_transpose<<<dim3(32, 32, 1), tb>>>(Wq, wt + 0 * (size_t)DD * DD, DD, DD, 0, 0);
    k_transpose<<<dim3(32, 32, 1), tb>>>(Wk, wt + 1 * (size_t)DD * DD, DD, DD, 0, 0);
    k_transpose<<<dim3(32, 32, 1), tb>>>(Wv, wt + 2 * (size_t)DD * DD, DD, DD, 0, 0);

    // QKV projections
    k_qkv<<<dim3(DD / 128, MS / 128, 3), 256, SMEM_BYTES>>>(x);

    // vt[b][e][j] = v[b][j][e]
    k_transpose<<<dim3(DD / 32, SS / 32, BB), tb>>>(
        vsrc, vt, SS, DD, (size_t)SS * DD, (size_t)DD * SS);

    // causal scores (lower-triangle tiles only)
    k_scores<<<dim3(SS / 128, SS / 128, BB), 256, SMEM_BYTES>>>();

    // column softmax (+ upper-triangle zeroing within diagonal tiles)
    k_softmax<<<dim3(SS / 32, BB), tb>>>();

    // weights @ V
    k_out<<<dim3(DD / 128, SS / 128, BB), 256, SMEM_BYTES>>>(out);
}

// round 5
// speedup vs baseline: 7.4237x; 2.6465x over previous
#include <cuda_runtime.h>
#include <cuda_fp16.h>
#include <cstdint>

#define BB 8
#define SS 2048
#define DD 1024
#define MS (BB * SS)   // 16384

// ---------------- scratch (device globals; no cudaMalloc allowed) ----------
__device__ __half g_xh[(size_t)MS * DD];        // 32 MB  x in fp16
__device__ __half g_wt[(size_t)3 * DD * DD];    //  6 MB  W^T fp16
__device__ __half g_qh[(size_t)MS * DD];        // 32 MB
__device__ __half g_kh[(size_t)MS * DD];        // 32 MB
__device__ __half g_vh[(size_t)MS * DD];        // 32 MB
__device__ __half g_vt[(size_t)BB * DD * SS];   // 32 MB  v^T per batch
__device__ float  g_s [(size_t)BB * SS * SS];   // 128 MB scores fp32
__device__ __half g_w [(size_t)BB * SS * SS];   // 64 MB  weights fp16

// ---------------- smem: 2 stages x (A 16KB + B 16KB) -----------------------
#define STAGE_B 32768
#define SMEM_BYTES (2 * STAGE_B)   // 65536

// ---------------- PTX helpers ----------------------------------------------
__device__ __forceinline__ uint32_t smem_u32(const void* p) {
    uint32_t a;
    asm("{ .reg .u64 t; cvta.to.shared.u64 t, %1; cvt.u32.u64 %0, t; }"
        : "=r"(a) : "l"(p));
    return a;
}
__device__ __forceinline__ void cpa16(uint32_t d, const void* s) {
    asm volatile("cp.async.cg.shared.global [%0], [%1], 16;"
                 :: "r"(d), "l"(s) : "memory");
}
#define CP_COMMIT() asm volatile("cp.async.commit_group;" ::: "memory")
#define CP_WAIT(n)  asm volatile("cp.async.wait_group %0;" :: "n"(n) : "memory")

__device__ __forceinline__ void ldsm_x4(uint32_t* r, uint32_t addr) {
    asm volatile("ldmatrix.sync.aligned.m8n8.x4.shared.b16 {%0,%1,%2,%3}, [%4];"
        : "=r"(r[0]), "=r"(r[1]), "=r"(r[2]), "=r"(r[3]) : "r"(addr));
}
__device__ __forceinline__ void mma16816(float* c, const uint32_t* a,
                                         const uint32_t* b) {
    asm volatile(
        "mma.sync.aligned.m16n8k16.row.col.f32.f16.f16.f32 "
        "{%0,%1,%2,%3}, {%4,%5,%6,%7}, {%8,%9}, {%0,%1,%2,%3};"
        : "+f"(c[0]), "+f"(c[1]), "+f"(c[2]), "+f"(c[3])
        : "r"(a[0]), "r"(a[1]), "r"(a[2]), "r"(a[3]), "r"(b[0]), "r"(b[1]));
}

// fill one stage: A/B tiles 128 rows x 64 fp16 (128B/row), SW128 swizzle
__device__ __forceinline__ void fill_stage(
    uint32_t sbase, int stg, const __half* A, int lda,
    const __half* B, int ldb, int k0, int tid)
{
    const uint32_t sA = sbase + stg * STAGE_B;
    const uint32_t sB = sA + 16384;
#pragma unroll
    for (int i = 0; i < 4; i++) {
        const int id = tid + (i << 8);
        const int r = id >> 3;
        const int c = id & 7;
        const uint32_t sw = (uint32_t)r * 128 + (uint32_t)((c ^ (r & 7)) << 4);
        cpa16(sA + sw, A + (size_t)r * lda + k0 + c * 8);
        cpa16(sB + sw, B + (size_t)r * ldb + k0 + c * 8);
    }
    CP_COMMIT();
}

// ---------------------------------------------------------------------------
// 128x128 tile GEMM:  C[m][n] = scale * sum_k A[m][k] * B[n][k]
// A,B fp16 K-major; kelems multiple of 64.
// MODE 0: write fp16; MODE 1: write fp32 scaled.
// ---------------------------------------------------------------------------
template<int MODE>
__device__ __forceinline__ void gemm_fp16(
    const __half* __restrict__ A, int lda,
    const __half* __restrict__ B, int ldb,
    void* __restrict__ Cv, int ldc, int kelems, float scale)
{
    extern __shared__ char sm[];
    const uint32_t sbase = smem_u32(sm);
    const int tid  = threadIdx.x;
    const int lane = tid & 31;
    const int wid  = tid >> 5;
    const int wm   = (wid & 1) * 64;
    const int wn   = (wid >> 1) * 32;

    // ldmatrix lane geometry
    const int ra = lane & 15;
    const int ca = (lane >> 4) * 16;                  // byte col within k16
    const int rb = (lane & 7) + (lane >> 4) * 8;
    const int cb = ((lane >> 3) & 1) * 16;

    float acc[4][4][4] = {};

    const int nc = kelems >> 6;
    fill_stage(sbase, 0, A, lda, B, ldb, 0, tid);

    for (int ch = 0; ch < nc; ch++) {
        const int s = ch & 1;
        if (ch + 1 < nc) {
            fill_stage(sbase, s ^ 1, A, lda, B, ldb, (ch + 1) << 6, tid);
            CP_WAIT(1);
        } else {
            CP_WAIT(0);
        }
        __syncthreads();

        const uint32_t sA = sbase + s * STAGE_B;
        const uint32_t sB = sA + 16384;
#pragma unroll
        for (int kk = 0; kk < 4; kk++) {
            uint32_t a[4][4], b[2][4];
#pragma unroll
            for (int mt = 0; mt < 4; mt++) {
                const int r = wm + mt * 16 + ra;
                const int col = kk * 32 + ca;
                ldsm_x4(a[mt], sA + (uint32_t)r * 128 +
                               (uint32_t)((((col >> 4) ^ (r & 7))) << 4));
            }
#pragma unroll
            for (int np = 0; np < 2; np++) {
                const int r = wn + np * 16 + rb;
                const int col = kk * 32 + cb;
                ldsm_x4(b[np], sB + (uint32_t)r * 128 +
                               (uint32_t)((((col >> 4) ^ (r & 7))) << 4));
            }
#pragma unroll
            for (int mt = 0; mt < 4; mt++)
#pragma unroll
                for (int nt = 0; nt < 4; nt++)
                    mma16816(acc[mt][nt], a[mt], &b[nt >> 1][(nt & 1) * 2]);
        }
        __syncthreads();
    }

    // epilogue
    const int er = lane >> 2;
    const int ec = (lane & 3) * 2;
#pragma unroll
    for (int mt = 0; mt < 4; mt++)
#pragma unroll
        for (int nt = 0; nt < 4; nt++) {
            const int r = wm + mt * 16 + er;
            const int cn = wn + nt * 8 + ec;
            if (MODE == 0) {
                __half* C = (__half*)Cv;
                *(__half2*)(C + (size_t)r * ldc + cn) =
                    __floats2half2_rn(acc[mt][nt][0], acc[mt][nt][1]);
                *(__half2*)(C + (size_t)(r + 8) * ldc + cn) =
                    __floats2half2_rn(acc[mt][nt][2], acc[mt][nt][3]);
            } else {
                float* C = (float*)Cv;
                *(float2*)(C + (size_t)r * ldc + cn) =
                    make_float2(acc[mt][nt][0] * scale, acc[mt][nt][1] * scale);
                *(float2*)(C + (size_t)(r + 8) * ldc + cn) =
                    make_float2(acc[mt][nt][2] * scale, acc[mt][nt][3] * scale);
            }
        }
}

// ---------------------------------------------------------------------------
// Pass kernels
// ---------------------------------------------------------------------------
__global__ __launch_bounds__(256, 2) void k_qkv()
{
    const __half* Bt = g_wt + (size_t)blockIdx.z * DD * DD
                            + (size_t)blockIdx.x * 128 * DD;
    __half* O = (blockIdx.z == 0) ? g_qh : (blockIdx.z == 1) ? g_kh : g_vh;
    gemm_fp16<0>(g_xh + (size_t)blockIdx.y * 128 * DD, DD,
                 Bt, DD,
                 O + (size_t)blockIdx.y * 128 * DD + blockIdx.x * 128, DD,
                 DD, 1.0f);
}

__global__ __launch_bounds__(256, 2) void k_scores()
{
    if (blockIdx.x > blockIdx.y) return;          // causal: lower tiles only
    const int b = blockIdx.z;
    gemm_fp16<1>(g_qh + (size_t)b * SS * DD + (size_t)blockIdx.y * 128 * DD, DD,
                 g_kh + (size_t)b * SS * DD + (size_t)blockIdx.x * 128 * DD, DD,
                 g_s + (size_t)b * SS * SS + (size_t)blockIdx.y * 128 * SS
                     + blockIdx.x * 128, SS,
                 DD, 0.03125f);                   // 1/sqrt(1024)
}

__global__ __launch_bounds__(256, 2) void k_out(float* __restrict__ out)
{
    const int b = blockIdx.z;
    const int m0 = blockIdx.y * 128;
    gemm_fp16<1>(g_w + (size_t)b * SS * SS + (size_t)m0 * SS, SS,
                 g_vt + (size_t)b * DD * SS + (size_t)blockIdx.x * 128 * SS, SS,
                 out + (size_t)b * SS * DD + (size_t)m0 * DD + blockIdx.x * 128,
                 DD, m0 + 128, 1.0f);             // causal K truncation
}

// ---------------------------------------------------------------------------
// x fp32 -> fp16
// ---------------------------------------------------------------------------
__global__ void k_cvtx(const float* __restrict__ x)
{
    const size_t i = ((size_t)blockIdx.x * 256 + threadIdx.x) * 4;
    float4 v = *(const float4*)(x + i);
    *(__half2*)(g_xh + i)     = __floats2half2_rn(v.x, v.y);
    *(__half2*)(g_xh + i + 2) = __floats2half2_rn(v.z, v.w);
}

// W fp32 [DD][DD] -> wt fp16 transposed
__global__ void k_wtr(const float* __restrict__ W, __half* __restrict__ ot)
{
    __shared__ float t[32][33];
    const int x0 = blockIdx.x * 32, y0 = blockIdx.y * 32;
    const int tx = threadIdx.x, ty = threadIdx.y;   // 32 x 8
#pragma unroll
    for (int i = 0; i < 32; i += 8)
        t[ty + i][tx] = W[(size_t)(y0 + ty + i) * DD + x0 + tx];
    __syncthreads();
#pragma unroll
    for (int i = 0; i < 32; i += 8)
        ot[(size_t)(x0 + ty + i) * DD + y0 + tx] = __float2half(t[tx][ty + i]);
}

// vh fp16 [b][SS][DD] -> vt fp16 [b][DD][SS]
__global__ void k_vtr()
{
    __shared__ __half t[32][34];
    const __half* ib = g_vh + (size_t)blockIdx.z * SS * DD;
    __half* ob = g_vt + (size_t)blockIdx.z * DD * SS;
    const int x0 = blockIdx.x * 32, y0 = blockIdx.y * 32;
    const int tx = threadIdx.x, ty = threadIdx.y;
#pragma unroll
    for (int i = 0; i < 32; i += 8)
        t[ty + i][tx] = ib[(size_t)(y0 + ty + i) * DD + x0 + tx];
    __syncthreads();
#pragma unroll
    for (int i = 0; i < 32; i += 8)
        ob[(size_t)(x0 + ty + i) * SS + y0 + tx] = t[tx][ty + i];
}

// ---------------------------------------------------------------------------
// Column softmax over query axis (axis=1). Column j normalizes over rows
// i in [j, S). Reads g_s fp32, writes g_w fp16 (zeroing i<j entries down to
// the 128-aligned tile base so the out-pass GEMM needs no predicate).
// ---------------------------------------------------------------------------
__global__ void k_softmax()
{
    const int b = blockIdx.y;
    const float* sb = g_s + (size_t)b * SS * SS;
    __half* wb = g_w + (size_t)b * SS * SS;
    const int tx = threadIdx.x;
    const int ty = threadIdx.y;
    const int j0 = blockIdx.x * 32;
    const int j = j0 + tx;
    const int ibase = (j0 & ~127);

    __shared__ float red[8][32];

    float mx = -INFINITY;
    for (int i = ibase + ty; i < SS; i += 8) {
        float v = sb[(size_t)i * SS + j];
        if (i >= j) mx = fmaxf(mx, v);
    }
    red[ty][tx] = mx;
    __syncthreads();
    if (ty == 0) {
        float m = red[0][tx];
#pragma unroll
        for (int r = 1; r < 8; r++) m = fmaxf(m, red[r][tx]);
        red[0][tx] = m;
    }
    __syncthreads();
    mx = red[0][tx];
    __syncthreads();

    float sum = 0.f;
    for (int i = ibase + ty; i < SS; i += 8) {
        float v = sb[(size_t)i * SS + j];
        if (i >= j) sum += __expf(v - mx);
    }
    red[ty][tx] = sum;
    __syncthreads();
    if (ty == 0) {
        float s = 0.f;
#pragma unroll
        for (int r = 0; r < 8; r++) s += red[r][tx];
        red[0][tx] = 1.0f / s;
    }
    __syncthreads();
    const float inv = red[0][tx];

    for (int i = ibase + ty; i < SS; i += 8) {
        float v = sb[(size_t)i * SS + j];
        wb[(size_t)i * SS + j] = (i >= j) ? __float2half(__expf(v - mx) * inv)
                                          : __half(0.0f);
    }
}

// ---------------------------------------------------------------------------
extern "C" void kernel_launch(void* const* d_in, const int* in_sizes, int n_in,
                              void* d_out, int out_size)
{
    const float* x  = (const float*)d_in[0];
    const float* Wq = (const float*)d_in[1];
    const float* Wk = (const float*)d_in[2];
    const float* Wv = (const float*)d_in[3];
    float* out = (float*)d_out;

    cudaFuncSetAttribute(k_qkv,    cudaFuncAttributeMaxDynamicSharedMemorySize, SMEM_BYTES);
    cudaFuncSetAttribute(k_scores, cudaFuncAttributeMaxDynamicSharedMemorySize, SMEM_BYTES);
    cudaFuncSetAttribute(k_out,    cudaFuncAttributeMaxDynamicSharedMemorySize, SMEM_BYTES);

    __half* wt; cudaGetSymbolAddress((void**)&wt, g_wt);

    dim3 tb(32, 8);

    // x -> fp16
    k_cvtx<<<MS * DD / 1024, 256>>>(x);

    // W transposes (fp32 -> fp16)
    k_wtr<<<dim3(32, 32), tb>>>(Wq, wt + 0 * (size_t)DD * DD);
    k_wtr<<<dim3(32, 32), tb>>>(Wk, wt + 1 * (size_t)DD * DD);
    k_wtr<<<dim3(32, 32), tb>>>(Wv, wt + 2 * (size_t)DD * DD);

    // QKV projections (fp16 in, fp16 out)
    k_qkv<<<dim3(DD / 128, MS / 128, 3), 256, SMEM_BYTES>>>();

    // v^T per batch
    k_vtr<<<dim3(DD / 32, SS / 32, BB), tb>>>();

    // causal scores (lower-triangle tiles only), fp32 out
    k_scores<<<dim3(SS / 128, SS / 128, BB), 256, SMEM_BYTES>>>();

    // column softmax -> fp16 weights (+ diagonal-tile upper-triangle zeroing)
    k_softmax<<<dim3(SS / 32, BB), tb>>>();

    // weights @ V
    k_out<<<dim3(DD / 128, SS / 128, BB), 256, SMEM_BYTES>>>(out);
}